// round 3
// baseline (speedup 1.0000x reference)
#include <cuda_runtime.h>
#include <cstdint>

// Problem constants (FullAttention: B=2, L=S=2048, H=16, E=D=64)
constexpr int B_ = 2, L_ = 2048, S_ = 2048, H_ = 16, E_ = 64, D_ = 64;
constexpr int BR = 64;   // q rows per CTA
constexpr int BC = 64;   // kv cols per tile
constexpr int KSTR = 68; // K/P smem row stride (floats) -> conflict-free b-frag loads
constexpr int VSTR = 72; // V smem row stride (floats)   -> conflict-free b-frag loads

__device__ int g_mask_nonzero;

__global__ void reset_flag_kernel() { g_mask_nonzero = 0; }

__global__ void scan_mask_kernel(const float4* __restrict__ m, int n4) {
    int any = 0;
    for (int i = blockIdx.x * blockDim.x + threadIdx.x; i < n4;
         i += gridDim.x * blockDim.x) {
        float4 v = m[i];
        any |= (v.x != 0.f) | (v.y != 0.f) | (v.z != 0.f) | (v.w != 0.f);
    }
    if (__syncthreads_or(any)) {
        if (threadIdx.x == 0) atomicOr(&g_mask_nonzero, 1);
    }
}

__device__ __forceinline__ uint32_t f2tf(float x) {
    uint32_t u;
    asm("cvt.rna.tf32.f32 %0, %1;" : "=r"(u) : "f"(x));
    return u;
}

__device__ __forceinline__ float ex2(float x) {
    float y;
    asm("ex2.approx.ftz.f32 %0, %1;" : "=f"(y) : "f"(x));
    return y;
}

__device__ __forceinline__ void mma8(float* c, const uint32_t* a, const uint32_t* b) {
    asm volatile(
        "mma.sync.aligned.m16n8k8.row.col.f32.tf32.tf32.f32 "
        "{%0,%1,%2,%3}, {%4,%5,%6,%7}, {%8,%9}, {%0,%1,%2,%3};"
        : "+f"(c[0]), "+f"(c[1]), "+f"(c[2]), "+f"(c[3])
        : "r"(a[0]), "r"(a[1]), "r"(a[2]), "r"(a[3]), "r"(b[0]), "r"(b[1]));
}

__global__ __launch_bounds__(128, 4)
void attn_kernel(const float* __restrict__ Q, const float* __restrict__ K,
                 const float* __restrict__ V, const float* __restrict__ M,
                 float* __restrict__ O) {
    __shared__ float sK[BC * KSTR];  // K tile; reused as P tile after QK^T
    __shared__ float sV[BC * VSTR];

    const int qt = blockIdx.x, h = blockIdx.y, b = blockIdx.z;
    const int tid = threadIdx.x;
    const int w = tid >> 5, lane = tid & 31;
    const int g = lane >> 2, t = lane & 3;
    const int maskflag = g_mask_nonzero;

    // --- Load Q fragments once (rows r0 and r0+8 of this warp's 16-row slice) ---
    const int r0 = qt * BR + w * 16 + g;
    const float* qp0 = Q + ((size_t)(b * L_ + r0) * H_ + h) * E_;
    const float* qp1 = qp0 + (size_t)8 * H_ * E_;
    uint32_t qa[8][4];
#pragma unroll
    for (int ks = 0; ks < 8; ks++) {
        qa[ks][0] = f2tf(qp0[ks * 8 + t]);
        qa[ks][1] = f2tf(qp1[ks * 8 + t]);
        qa[ks][2] = f2tf(qp0[ks * 8 + t + 4]);
        qa[ks][3] = f2tf(qp1[ks * 8 + t + 4]);
    }

    float o[8][4];
#pragma unroll
    for (int n = 0; n < 8; n++)
#pragma unroll
        for (int i = 0; i < 4; i++) o[n][i] = 0.f;
    float mrow[2] = {-1e30f, -1e30f};
    float lrow[2] = {0.f, 0.f};
    const float cs = 0.125f * 1.4426950408889634f;  // scale * log2(e)

    const float* kb = K + ((size_t)(b * S_) * H_ + h) * E_;
    const float* vb = V + ((size_t)(b * S_) * H_ + h) * D_;

    for (int kt = 0; kt < S_ / BC; kt++) {
        __syncthreads();  // previous iteration's PV reads done

        // --- Cooperative load of K,V tiles (cvt to tf32 on the fly) ---
#pragma unroll
        for (int i = 0; i < 8; i++) {
            int idx = tid + i * 128;           // 0..1023
            int row = idx >> 4;                // 0..63
            int c4 = (idx & 15) << 2;          // 0,4,..,60
            const size_t srow = (size_t)(kt * BC + row);
            float4 k4 = *(const float4*)(kb + srow * H_ * E_ + c4);
            float4 v4 = *(const float4*)(vb + srow * H_ * D_ + c4);
            float4 kk, vv;
            kk.x = __uint_as_float(f2tf(k4.x)); kk.y = __uint_as_float(f2tf(k4.y));
            kk.z = __uint_as_float(f2tf(k4.z)); kk.w = __uint_as_float(f2tf(k4.w));
            vv.x = __uint_as_float(f2tf(v4.x)); vv.y = __uint_as_float(f2tf(v4.y));
            vv.z = __uint_as_float(f2tf(v4.z)); vv.w = __uint_as_float(f2tf(v4.w));
            *(float4*)&sK[row * KSTR + c4] = kk;
            *(float4*)&sV[row * VSTR + c4] = vv;
        }
        __syncthreads();

        // --- S = Q K^T (16x64 per warp) ---
        float sc[8][4];
#pragma unroll
        for (int n = 0; n < 8; n++)
#pragma unroll
            for (int i = 0; i < 4; i++) sc[n][i] = 0.f;
#pragma unroll
        for (int n = 0; n < 8; n++) {
#pragma unroll
            for (int ks = 0; ks < 8; ks++) {
                uint32_t bf[2];
                const float* kp = &sK[(n * 8 + g) * KSTR + ks * 8 + t];
                bf[0] = __float_as_uint(kp[0]);
                bf[1] = __float_as_uint(kp[4]);
                mma8(sc[n], qa[ks], bf);
            }
        }
        __syncthreads();  // everyone done reading sK -> safe to overwrite with P

        // --- optional additive mask (slow path; mask is usually all-zero) ---
        if (maskflag) {
            const float* mp0 = M + (size_t)r0 * S_ + kt * BC;
            const float* mp1 = mp0 + (size_t)8 * S_;
#pragma unroll
            for (int n = 0; n < 8; n++) {
                float2 m0 = *(const float2*)&mp0[n * 8 + 2 * t];
                float2 m1 = *(const float2*)&mp1[n * 8 + 2 * t];
                sc[n][0] += m0.x; sc[n][1] += m0.y;
                sc[n][2] += m1.x; sc[n][3] += m1.y;
            }
        }

        // --- online softmax (exp2 units, scale folded) ---
#pragma unroll
        for (int n = 0; n < 8; n++)
#pragma unroll
            for (int i = 0; i < 4; i++) sc[n][i] *= cs;

        float mnew[2], al[2];
#pragma unroll
        for (int r = 0; r < 2; r++) {
            float mx = mrow[r];
#pragma unroll
            for (int n = 0; n < 8; n++)
                mx = fmaxf(mx, fmaxf(sc[n][2 * r], sc[n][2 * r + 1]));
            mx = fmaxf(mx, __shfl_xor_sync(0xffffffffu, mx, 1));
            mx = fmaxf(mx, __shfl_xor_sync(0xffffffffu, mx, 2));
            mnew[r] = mx;
            al[r] = ex2(mrow[r] - mx);
            mrow[r] = mx;
        }

        float ls[2] = {0.f, 0.f};
#pragma unroll
        for (int n = 0; n < 8; n++) {
#pragma unroll
            for (int i = 0; i < 4; i++) {
                int r = i >> 1;
                float p = ex2(sc[n][i] - mnew[r]);
                p = __uint_as_float(f2tf(p));  // tf32-round so numerator/denominator agree
                sc[n][i] = p;
                ls[r] += p;
            }
        }
#pragma unroll
        for (int r = 0; r < 2; r++) {
            ls[r] += __shfl_xor_sync(0xffffffffu, ls[r], 1);
            ls[r] += __shfl_xor_sync(0xffffffffu, ls[r], 2);
            lrow[r] = lrow[r] * al[r] + ls[r];
        }
#pragma unroll
        for (int n = 0; n < 8; n++) {
            o[n][0] *= al[0]; o[n][1] *= al[0];
            o[n][2] *= al[1]; o[n][3] *= al[1];
        }

        // --- P -> smem (per-warp private 16 rows of the K buffer) ---
        float* pr0 = &sK[(w * 16 + g) * KSTR];
        float* pr1 = pr0 + 8 * KSTR;
#pragma unroll
        for (int n = 0; n < 8; n++) {
            *(float2*)&pr0[n * 8 + 2 * t] = make_float2(sc[n][0], sc[n][1]);
            *(float2*)&pr1[n * 8 + 2 * t] = make_float2(sc[n][2], sc[n][3]);
        }
        __syncwarp();

        // --- O += P V ---
#pragma unroll
        for (int ks = 0; ks < 8; ks++) {
            uint32_t pa[4];
            const float* pp = &sK[(w * 16 + g) * KSTR + ks * 8 + t];
            pa[0] = __float_as_uint(pp[0]);
            pa[1] = __float_as_uint(pp[8 * KSTR]);
            pa[2] = __float_as_uint(pp[4]);
            pa[3] = __float_as_uint(pp[8 * KSTR + 4]);
#pragma unroll
            for (int n = 0; n < 8; n++) {
                uint32_t vf[2];
                const float* vp = &sV[(ks * 8 + t) * VSTR + n * 8 + g];
                vf[0] = __float_as_uint(vp[0]);
                vf[1] = __float_as_uint(vp[4 * VSTR]);
                mma8(o[n], pa, vf);
            }
        }
    }

    // --- epilogue: normalize and store [B,L,H,D] ---
    const float rl0 = 1.f / lrow[0];
    const float rl1 = 1.f / lrow[1];
    float* op0 = O + ((size_t)(b * L_ + r0) * H_ + h) * D_;
    float* op1 = op0 + (size_t)8 * H_ * D_;
#pragma unroll
    for (int n = 0; n < 8; n++) {
        *(float2*)&op0[n * 8 + 2 * t] = make_float2(o[n][0] * rl0, o[n][1] * rl0);
        *(float2*)&op1[n * 8 + 2 * t] = make_float2(o[n][2] * rl1, o[n][3] * rl1);
    }
}

extern "C" void kernel_launch(void* const* d_in, const int* in_sizes, int n_in,
                              void* d_out, int out_size) {
    const float* Q = (const float*)d_in[0];
    const float* K = (const float*)d_in[1];
    const float* V = (const float*)d_in[2];
    const float* M = (const float*)d_in[3];
    float* O = (float*)d_out;

    reset_flag_kernel<<<1, 1>>>();
    scan_mask_kernel<<<256, 256>>>((const float4*)M, (L_ * S_) / 4);

    dim3 grid(L_ / BR, H_, B_);
    attn_kernel<<<grid, 128>>>(Q, K, V, M, O);
}

// round 4
// speedup vs baseline: 1.1018x; 1.1018x over previous
#include <cuda_runtime.h>
#include <cstdint>

// Problem constants (FullAttention: B=2, L=S=2048, H=16, E=D=64)
constexpr int B_ = 2, L_ = 2048, S_ = 2048, H_ = 16, E_ = 64, D_ = 64;
constexpr int BR = 128;  // q rows per CTA (32 per warp, 2 m-tiles)
constexpr int BC = 64;   // kv cols per tile
constexpr int KSTR = 68; // K/P smem row stride (floats) -> conflict-free b-frag loads
constexpr int VSTR = 72; // V smem row stride (floats)   -> conflict-free b-frag loads
constexpr int SMEM_BYTES = (BC * KSTR + BC * VSTR + BR * KSTR) * 4;  // 70656

__device__ int g_mask_nonzero;

__global__ void reset_flag_kernel() { g_mask_nonzero = 0; }

__global__ void scan_mask_kernel(const float4* __restrict__ m, int n4) {
    int any = 0;
    for (int i = blockIdx.x * blockDim.x + threadIdx.x; i < n4;
         i += gridDim.x * blockDim.x) {
        float4 v = m[i];
        any |= (v.x != 0.f) | (v.y != 0.f) | (v.z != 0.f) | (v.w != 0.f);
    }
    if (__syncthreads_or(any)) {
        if (threadIdx.x == 0) atomicOr(&g_mask_nonzero, 1);
    }
}

__device__ __forceinline__ uint32_t f2tf(float x) {
    uint32_t u;
    asm("cvt.rna.tf32.f32 %0, %1;" : "=r"(u) : "f"(x));
    return u;
}

__device__ __forceinline__ float ex2(float x) {
    float y;
    asm("ex2.approx.ftz.f32 %0, %1;" : "=f"(y) : "f"(x));
    return y;
}

__device__ __forceinline__ void mma8(float* c, const uint32_t* a, const uint32_t* b) {
    asm volatile(
        "mma.sync.aligned.m16n8k8.row.col.f32.tf32.tf32.f32 "
        "{%0,%1,%2,%3}, {%4,%5,%6,%7}, {%8,%9}, {%0,%1,%2,%3};"
        : "+f"(c[0]), "+f"(c[1]), "+f"(c[2]), "+f"(c[3])
        : "r"(a[0]), "r"(a[1]), "r"(a[2]), "r"(a[3]), "r"(b[0]), "r"(b[1]));
}

__global__ __launch_bounds__(128, 2)
void attn_kernel(const float* __restrict__ Q, const float* __restrict__ K,
                 const float* __restrict__ V, const float* __restrict__ M,
                 float* __restrict__ O) {
    extern __shared__ float smem[];
    float* sK = smem;                   // [BC * KSTR]
    float* sV = sK + BC * KSTR;         // [BC * VSTR]
    float* sP = sV + BC * VSTR;         // [BR * KSTR], warp-private row bands

    const int qt = blockIdx.x, h = blockIdx.y, b = blockIdx.z;
    const int tid = threadIdx.x;
    const int w = tid >> 5, lane = tid & 31;
    const int g = lane >> 2, t = lane & 3;
    const int maskflag = g_mask_nonzero;

    const int rw = qt * BR + w * 32;  // warp's first q row

    // --- Load Q fragments once: 2 m-tiles x 8 k-slices ---
    uint32_t qa[2][8][4];
#pragma unroll
    for (int mt = 0; mt < 2; mt++) {
        const int r0 = rw + mt * 16 + g;
        const float* qp0 = Q + ((size_t)(b * L_ + r0) * H_ + h) * E_;
        const float* qp1 = qp0 + (size_t)8 * H_ * E_;
#pragma unroll
        for (int ks = 0; ks < 8; ks++) {
            qa[mt][ks][0] = f2tf(qp0[ks * 8 + t]);
            qa[mt][ks][1] = f2tf(qp1[ks * 8 + t]);
            qa[mt][ks][2] = f2tf(qp0[ks * 8 + t + 4]);
            qa[mt][ks][3] = f2tf(qp1[ks * 8 + t + 4]);
        }
    }

    float o[2][8][4];
#pragma unroll
    for (int mt = 0; mt < 2; mt++)
#pragma unroll
        for (int n = 0; n < 8; n++)
#pragma unroll
            for (int i = 0; i < 4; i++) o[mt][n][i] = 0.f;
    float mrow[2][2] = {{-1e30f, -1e30f}, {-1e30f, -1e30f}};
    float lrow[2][2] = {{0.f, 0.f}, {0.f, 0.f}};
    const float cs = 0.125f * 1.4426950408889634f;  // scale * log2(e)

    const float* kb = K + ((size_t)(b * S_) * H_ + h) * E_;
    const float* vb = V + ((size_t)(b * S_) * H_ + h) * D_;

    for (int kt = 0; kt < S_ / BC; kt++) {
        __syncthreads();  // previous iteration's QK^T/PV smem reads done

        // --- Cooperative load of K,V tiles (cvt to tf32 on the fly) ---
#pragma unroll
        for (int i = 0; i < 8; i++) {
            int idx = tid + i * 128;           // 0..1023
            int row = idx >> 4;                // 0..63
            int c4 = (idx & 15) << 2;          // 0,4,..,60
            const size_t srow = (size_t)(kt * BC + row);
            float4 k4 = *(const float4*)(kb + srow * H_ * E_ + c4);
            float4 v4 = *(const float4*)(vb + srow * H_ * D_ + c4);
            float4 kk, vv;
            kk.x = __uint_as_float(f2tf(k4.x)); kk.y = __uint_as_float(f2tf(k4.y));
            kk.z = __uint_as_float(f2tf(k4.z)); kk.w = __uint_as_float(f2tf(k4.w));
            vv.x = __uint_as_float(f2tf(v4.x)); vv.y = __uint_as_float(f2tf(v4.y));
            vv.z = __uint_as_float(f2tf(v4.z)); vv.w = __uint_as_float(f2tf(v4.w));
            *(float4*)&sK[row * KSTR + c4] = kk;
            *(float4*)&sV[row * VSTR + c4] = vv;
        }
        __syncthreads();

        // --- S = Q K^T (32x64 per warp, B frag shared by both m-tiles) ---
        float sc[2][8][4];
#pragma unroll
        for (int mt = 0; mt < 2; mt++)
#pragma unroll
            for (int n = 0; n < 8; n++)
#pragma unroll
                for (int i = 0; i < 4; i++) sc[mt][n][i] = 0.f;
#pragma unroll
        for (int n = 0; n < 8; n++) {
#pragma unroll
            for (int ks = 0; ks < 8; ks++) {
                uint32_t bf[2];
                const float* kp = &sK[(n * 8 + g) * KSTR + ks * 8 + t];
                bf[0] = __float_as_uint(kp[0]);
                bf[1] = __float_as_uint(kp[4]);
                mma8(sc[0][n], qa[0][ks], bf);
                mma8(sc[1][n], qa[1][ks], bf);
            }
        }

        // --- optional additive mask (slow path; mask is usually all-zero) ---
        if (maskflag) {
#pragma unroll
            for (int mt = 0; mt < 2; mt++) {
                const int r0 = rw + mt * 16 + g;
                const float* mp0 = M + (size_t)r0 * S_ + kt * BC;
                const float* mp1 = mp0 + (size_t)8 * S_;
#pragma unroll
                for (int n = 0; n < 8; n++) {
                    float2 m0 = *(const float2*)&mp0[n * 8 + 2 * t];
                    float2 m1 = *(const float2*)&mp1[n * 8 + 2 * t];
                    sc[mt][n][0] += m0.x; sc[mt][n][1] += m0.y;
                    sc[mt][n][2] += m1.x; sc[mt][n][3] += m1.y;
                }
            }
        }

        // --- online softmax (exp2 units, scale folded) ---
#pragma unroll
        for (int mt = 0; mt < 2; mt++)
#pragma unroll
            for (int n = 0; n < 8; n++)
#pragma unroll
                for (int i = 0; i < 4; i++) sc[mt][n][i] *= cs;

#pragma unroll
        for (int mt = 0; mt < 2; mt++) {
#pragma unroll
            for (int r = 0; r < 2; r++) {
                float mx = mrow[mt][r];
#pragma unroll
                for (int n = 0; n < 8; n++)
                    mx = fmaxf(mx, fmaxf(sc[mt][n][2 * r], sc[mt][n][2 * r + 1]));
                mx = fmaxf(mx, __shfl_xor_sync(0xffffffffu, mx, 1));
                mx = fmaxf(mx, __shfl_xor_sync(0xffffffffu, mx, 2));
                float al = ex2(mrow[mt][r] - mx);
                mrow[mt][r] = mx;
                float ls = 0.f;
#pragma unroll
                for (int n = 0; n < 8; n++) {
                    float p0 = ex2(sc[mt][n][2 * r] - mx);
                    float p1 = ex2(sc[mt][n][2 * r + 1] - mx);
                    p0 = __uint_as_float(f2tf(p0));  // tf32-round: num/denom agree
                    p1 = __uint_as_float(f2tf(p1));
                    sc[mt][n][2 * r] = p0;
                    sc[mt][n][2 * r + 1] = p1;
                    ls += p0 + p1;
                }
                ls += __shfl_xor_sync(0xffffffffu, ls, 1);
                ls += __shfl_xor_sync(0xffffffffu, ls, 2);
                lrow[mt][r] = lrow[mt][r] * al + ls;
#pragma unroll
                for (int n = 0; n < 8; n++) {
                    o[mt][n][2 * r] *= al;
                    o[mt][n][2 * r + 1] *= al;
                }
            }
        }

        // --- P -> smem (warp-private 32-row band of sP) ---
#pragma unroll
        for (int mt = 0; mt < 2; mt++) {
            float* pr0 = &sP[(w * 32 + mt * 16 + g) * KSTR];
            float* pr1 = pr0 + 8 * KSTR;
#pragma unroll
            for (int n = 0; n < 8; n++) {
                *(float2*)&pr0[n * 8 + 2 * t] = make_float2(sc[mt][n][0], sc[mt][n][1]);
                *(float2*)&pr1[n * 8 + 2 * t] = make_float2(sc[mt][n][2], sc[mt][n][3]);
            }
        }
        __syncwarp();

        // --- O += P V (V frag shared by both m-tiles) ---
#pragma unroll
        for (int ks = 0; ks < 8; ks++) {
            uint32_t pa[2][4];
#pragma unroll
            for (int mt = 0; mt < 2; mt++) {
                const float* pp = &sP[(w * 32 + mt * 16 + g) * KSTR + ks * 8 + t];
                pa[mt][0] = __float_as_uint(pp[0]);
                pa[mt][1] = __float_as_uint(pp[8 * KSTR]);
                pa[mt][2] = __float_as_uint(pp[4]);
                pa[mt][3] = __float_as_uint(pp[8 * KSTR + 4]);
            }
#pragma unroll
            for (int n = 0; n < 8; n++) {
                uint32_t vf[2];
                const float* vp = &sV[(ks * 8 + t) * VSTR + n * 8 + g];
                vf[0] = __float_as_uint(vp[0]);
                vf[1] = __float_as_uint(vp[4 * VSTR]);
                mma8(o[0][n], pa[0], vf);
                mma8(o[1][n], pa[1], vf);
            }
        }
    }

    // --- epilogue: normalize and store [B,L,H,D] ---
#pragma unroll
    for (int mt = 0; mt < 2; mt++) {
        const float rl0 = 1.f / lrow[mt][0];
        const float rl1 = 1.f / lrow[mt][1];
        const int r0 = rw + mt * 16 + g;
        float* op0 = O + ((size_t)(b * L_ + r0) * H_ + h) * D_;
        float* op1 = op0 + (size_t)8 * H_ * D_;
#pragma unroll
        for (int n = 0; n < 8; n++) {
            *(float2*)&op0[n * 8 + 2 * t] = make_float2(o[mt][n][0] * rl0, o[mt][n][1] * rl0);
            *(float2*)&op1[n * 8 + 2 * t] = make_float2(o[mt][n][2] * rl1, o[mt][n][3] * rl1);
        }
    }
}

extern "C" void kernel_launch(void* const* d_in, const int* in_sizes, int n_in,
                              void* d_out, int out_size) {
    const float* Q = (const float*)d_in[0];
    const float* K = (const float*)d_in[1];
    const float* V = (const float*)d_in[2];
    const float* M = (const float*)d_in[3];
    float* O = (float*)d_out;

    cudaFuncSetAttribute(attn_kernel,
                         cudaFuncAttributeMaxDynamicSharedMemorySize, SMEM_BYTES);

    reset_flag_kernel<<<1, 1>>>();
    scan_mask_kernel<<<256, 256>>>((const float4*)M, (L_ * S_) / 4);

    dim3 grid(L_ / BR, H_, B_);
    attn_kernel<<<grid, 128, SMEM_BYTES>>>(Q, K, V, M, O);
}